// round 6
// baseline (speedup 1.0000x reference)
#include <cuda_runtime.h>
#include <cuda_fp16.h>
#include <cstdint>

// LSTM cell: fp16 GEMM with fp16 accumulators (periodic fp32 flush) via
// mma.sync + fused gate epilogue. out = [h | h | c].
// B columns permuted: col' = 4*u + gate.

#define MB   8192
#define KK   1024
#define NTOT 2048
#define UU   512
#define BM   128
#define BN   128
#define BK   32
#define KT   (KK / BK)              // 32 k-iterations
#define ROWB 80
#define TILEB (128 * ROWB)
#define STAGEB (2 * TILEB)
#define NSTG 4
#define SMEM_DYN (NSTG * STAGEB)    // 81920

// -------- device scratch --------
__device__ __half g_A[(size_t)MB * KK];
__device__ __half g_B[(size_t)NTOT * KK];

// -------- helpers --------
__device__ __forceinline__ uint32_t s2u(const void* p) {
    uint32_t a;
    asm("{ .reg .u64 t; cvta.to.shared.u64 t, %1; cvt.u32.u64 %0, t; }"
        : "=r"(a) : "l"(p));
    return a;
}
__device__ __forceinline__ void cp16(uint32_t dst, const void* src) {
    asm volatile("cp.async.cg.shared.global [%0], [%1], 16;"
                 :: "r"(dst), "l"((unsigned long long)__cvta_generic_to_global(src))
                 : "memory");
}
#define CP_COMMIT() asm volatile("cp.async.commit_group;" ::: "memory")
#define CP_WAIT2()  asm volatile("cp.async.wait_group 2;" ::: "memory")

__device__ __forceinline__ void ldsm4(uint32_t* r, uint32_t addr) {
    asm volatile("ldmatrix.sync.aligned.m8n8.x4.shared.b16 {%0,%1,%2,%3}, [%4];"
                 : "=r"(r[0]), "=r"(r[1]), "=r"(r[2]), "=r"(r[3]) : "r"(addr));
}
// fp16-accumulator MMA: D,C are 2 regs of fp16x2
__device__ __forceinline__ void mma16816h(uint32_t* c, const uint32_t* a,
                                          const uint32_t* b) {
    asm volatile(
        "mma.sync.aligned.m16n8k16.row.col.f16.f16.f16.f16 "
        "{%0,%1}, {%2,%3,%4,%5}, {%6,%7}, {%0,%1};"
        : "+r"(c[0]), "+r"(c[1])
        : "r"(a[0]), "r"(a[1]), "r"(a[2]), "r"(a[3]), "r"(b[0]), "r"(b[1]));
}
__device__ __forceinline__ float ex2f(float x) {
    float y; asm("ex2.approx.f32 %0, %1;" : "=f"(y) : "f"(x)); return y;
}
__device__ __forceinline__ float rcpf(float x) {
    float y; asm("rcp.approx.f32 %0, %1;" : "=f"(y) : "f"(x)); return y;
}
__device__ __forceinline__ float sigf(float x) {
    return rcpf(1.0f + ex2f(-1.4426950408889634f * x));
}
__device__ __forceinline__ float tanhf_fast(float x) {
    return 1.0f - 2.0f * rcpf(1.0f + ex2f(2.8853900817779268f * x));
}

// -------- conversion kernels --------
__global__ __launch_bounds__(256)
void conv_a(const float* __restrict__ X, const float* __restrict__ H)
{
    int idx = blockIdx.x * 256 + threadIdx.x;   // oct index, 1M total
    int row = idx >> 7;
    int c8  = (idx & 127) * 8;
    const float4* src = (c8 < 512)
        ? (const float4*)(X + (size_t)row * 512 + c8)
        : (const float4*)(H + (size_t)row * 512 + (c8 - 512));
    float4 v0 = src[0], v1 = src[1];
    __half h[8];
    h[0] = __float2half(v0.x); h[1] = __float2half(v0.y);
    h[2] = __float2half(v0.z); h[3] = __float2half(v0.w);
    h[4] = __float2half(v1.x); h[5] = __float2half(v1.y);
    h[6] = __float2half(v1.z); h[7] = __float2half(v1.w);
    ((uint4*)g_A)[idx] = *(uint4*)h;
}

// coalesced transpose version: block = 32 colp x 64 k
__global__ __launch_bounds__(256)
void conv_b(const float* __restrict__ W, const float* __restrict__ R)
{
    __shared__ __half s[64][34];
    const int c0 = blockIdx.x * 32;
    const int k0 = blockIdx.y * 64;
    #pragma unroll
    for (int i = 0; i < 8; ++i) {
        int idx = threadIdx.x + i * 256;   // 0..2047
        int kl = idx >> 5, cl = idx & 31;
        int colp = c0 + cl, u = colp >> 2, gate = colp & 3;
        int zcol = gate * 512 + u;
        int k = k0 + kl;
        float v = (k < 512) ? W[(size_t)k * NTOT + zcol]
                            : R[(size_t)(k - 512) * NTOT + zcol];
        s[kl][cl] = __float2half(v);
    }
    __syncthreads();
    const int cl = threadIdx.x >> 3;          // 0..31
    const int ks = (threadIdx.x & 7) * 8;     // 0..56
    __half tmp[8];
    #pragma unroll
    for (int j = 0; j < 8; ++j) tmp[j] = s[ks + j][cl];
    *(uint4*)&g_B[(size_t)(c0 + cl) * KK + k0 + ks] = *(uint4*)tmp;
}

// -------- fused GEMM + gates --------
__global__ __launch_bounds__(256, 2)
void lstm_mma(const float* __restrict__ Cprev,
              const float* __restrict__ bias,
              float* __restrict__ out)
{
    extern __shared__ __align__(128) char smem[];
    const uint32_t sm = s2u(smem);
    const int tid = threadIdx.x, wid = tid >> 5, lane = tid & 31;
    const int warp_m = wid >> 2;            // 0..1
    const int warp_n = wid & 3;             // 0..3
    const int m0 = blockIdx.y * BM;
    const int n0 = blockIdx.x * BN;

    float    accf[4][4][4];                 // fp32 masters
    uint32_t acch[4][4][2];                 // fp16x2 running accs
    #pragma unroll
    for (int mi = 0; mi < 4; ++mi)
        #pragma unroll
        for (int ni = 0; ni < 4; ++ni) {
            #pragma unroll
            for (int r = 0; r < 4; ++r) accf[mi][ni][r] = 0.0f;
            acch[mi][ni][0] = 0; acch[mi][ni][1] = 0;
        }

    const int lr0 = tid >> 2, lseg = tid & 3;

    auto load_stage = [&](int t, int stg) {
        const uint32_t sb = sm + stg * STAGEB;
        const int kb = t * BK;
        #pragma unroll
        for (int j = 0; j < 2; ++j) {
            int r = lr0 + j * 64;
            uint32_t dst = sb + r * ROWB + lseg * 16;
            cp16(dst,         g_A + (size_t)(m0 + r) * KK + kb + lseg * 8);
            cp16(dst + TILEB, g_B + (size_t)(n0 + r) * KK + kb + lseg * 8);
        }
    };

    load_stage(0, 0); CP_COMMIT();
    load_stage(1, 1); CP_COMMIT();
    load_stage(2, 2); CP_COMMIT();

    const uint32_t aoff = (warp_m * 64 + (lane & 15)) * ROWB + ((lane >> 4) << 4);
    const uint32_t boff = TILEB
        + (warp_n * 32 + (lane & 7) + ((lane & 16) >> 1)) * ROWB + ((lane & 8) << 1);

    for (int t = 0; t < KT; ++t) {
        CP_WAIT2();
        __syncthreads();

        const uint32_t sb = sm + (t & 3) * STAGEB;
        #pragma unroll
        for (int ks = 0; ks < 2; ++ks) {
            const uint32_t kB = ks * 32;
            uint32_t bh[2][4];
            #pragma unroll
            for (int nj = 0; nj < 2; ++nj)
                ldsm4(bh[nj], sb + boff + nj * (16 * ROWB) + kB);
            #pragma unroll
            for (int mi = 0; mi < 4; ++mi) {
                uint32_t ah[4];
                ldsm4(ah, sb + aoff + mi * (16 * ROWB) + kB);
                #pragma unroll
                for (int ni = 0; ni < 4; ++ni)
                    mma16816h(acch[mi][ni], ah, &bh[ni >> 1][(ni & 1) * 2]);
            }
        }

        if (t & 1) {  // flush fp16 accs -> fp32 masters every 4 MMAs (K=64)
            #pragma unroll
            for (int mi = 0; mi < 4; ++mi)
                #pragma unroll
                for (int ni = 0; ni < 4; ++ni) {
                    float2 p0 = __half22float2(*(__half2*)&acch[mi][ni][0]);
                    float2 p1 = __half22float2(*(__half2*)&acch[mi][ni][1]);
                    accf[mi][ni][0] += p0.x; accf[mi][ni][1] += p0.y;
                    accf[mi][ni][2] += p1.x; accf[mi][ni][3] += p1.y;
                    acch[mi][ni][0] = 0;     acch[mi][ni][1] = 0;
                }
        }

        if (t + 3 < KT) load_stage(t + 3, (t + 3) & 3);
        CP_COMMIT();
    }

    // ---- epilogue: stage z through smem ----
    __syncthreads();
    float* zs = (float*)smem;               // [128][132]
    const int g = lane >> 2, c2 = (lane & 3) * 2;
    #pragma unroll
    for (int mi = 0; mi < 4; ++mi) {
        const int r0 = warp_m * 64 + mi * 16 + g;
        #pragma unroll
        for (int ni = 0; ni < 4; ++ni) {
            const int col = warp_n * 32 + ni * 8 + c2;
            zs[r0 * 132 + col]           = accf[mi][ni][0];
            zs[r0 * 132 + col + 1]       = accf[mi][ni][1];
            zs[(r0 + 8) * 132 + col]     = accf[mi][ni][2];
            zs[(r0 + 8) * 132 + col + 1] = accf[mi][ni][3];
        }
    }
    __syncthreads();

    const size_t BU = (size_t)MB * UU;
    #pragma unroll
    for (int i = 0; i < 16; ++i) {
        int q   = tid + i * 256;
        int row = q >> 5;
        int ul  = q & 31;
        float4 zq = *(float4*)&zs[row * 132 + ul * 4];
        int u = blockIdx.x * 32 + ul;
        float zi = zq.x + __ldg(bias + u);
        float zf = zq.y + __ldg(bias + 512 + u);
        float zg = zq.z + __ldg(bias + 1024 + u);
        float zo = zq.w + __ldg(bias + 1536 + u);
        float cp = Cprev[(size_t)(m0 + row) * UU + u];
        float cn = sigf(zf) * cp + sigf(zi) * tanhf_fast(zg);
        float hv = sigf(zo) * tanhf_fast(cn);
        size_t o = (size_t)(m0 + row) * UU + u;
        out[o]          = hv;
        out[o + BU]     = hv;
        out[o + 2 * BU] = cn;
    }
}

// -------- launch --------
extern "C" void kernel_launch(void* const* d_in, const int* in_sizes, int n_in,
                              void* d_out, int out_size)
{
    const float* X    = (const float*)d_in[0];
    const float* H    = (const float*)d_in[1];
    const float* C    = (const float*)d_in[2];
    const float* W    = (const float*)d_in[3];
    const float* R    = (const float*)d_in[4];
    const float* bias = (const float*)d_in[5];
    float* out = (float*)d_out;

    static bool attr_done = false;
    if (!attr_done) {
        cudaFuncSetAttribute(lstm_mma,
                             cudaFuncAttributeMaxDynamicSharedMemorySize, SMEM_DYN);
        attr_done = true;
    }

    conv_a<<<MB * KK / 8 / 256, 256>>>(X, H);
    dim3 bgrid(NTOT / 32, KK / 64);          // (64, 16)
    conv_b<<<bgrid, 256>>>(W, R);

    dim3 grid(NTOT / BN, MB / BM);           // (16, 64)
    lstm_mma<<<grid, 256, SMEM_DYN>>>(C, bias, out);
}

// round 7
// speedup vs baseline: 1.1989x; 1.1989x over previous
#include <cuda_runtime.h>
#include <cuda_fp16.h>
#include <cstdint>

// LSTM cell: single-pass fp16 GEMM (fp32 acc) via mma.sync + fused gate
// epilogue. z = [X|H] @ [W;R] (+bias); out = [h | h | c].
// B columns permuted: col' = 4*u + gate -> BN=128 tile holds 32 gate quads.
// Conversions (fp32 -> fp16, A concat + B transpose/permute) merged into one
// kernel launch.

#define MB   8192
#define KK   1024
#define NTOT 2048
#define UU   512
#define BM   128
#define BN   128
#define BK   32
#define KT   (KK / BK)              // 32 k-iterations
#define ROWB 80                     // smem row stride bytes (64B data + 16 pad)
#define TILEB (128 * ROWB)          // 10240 per [128 x 32] fp16 tile
#define STAGEB (2 * TILEB)          // A, B
#define NSTG 4
#define SMEM_DYN (NSTG * STAGEB)    // 81920; epilogue z-stage (67584) reuses it

#define CONVA_BLOCKS (MB * KK / 8 / 256)   // 4096
#define CONVB_BX     (NTOT / 32)           // 64
#define CONVB_BY     (KK / 64)             // 16
#define CONVB_BLOCKS (CONVB_BX * CONVB_BY) // 1024

// -------- device scratch --------
__device__ __half g_A[(size_t)MB * KK];
__device__ __half g_B[(size_t)NTOT * KK];

// -------- helpers --------
__device__ __forceinline__ uint32_t s2u(const void* p) {
    uint32_t a;
    asm("{ .reg .u64 t; cvta.to.shared.u64 t, %1; cvt.u32.u64 %0, t; }"
        : "=r"(a) : "l"(p));
    return a;
}
__device__ __forceinline__ void cp16(uint32_t dst, const void* src) {
    asm volatile("cp.async.cg.shared.global [%0], [%1], 16;"
                 :: "r"(dst), "l"((unsigned long long)__cvta_generic_to_global(src))
                 : "memory");
}
#define CP_COMMIT() asm volatile("cp.async.commit_group;" ::: "memory")
#define CP_WAIT2()  asm volatile("cp.async.wait_group 2;" ::: "memory")

__device__ __forceinline__ void ldsm4(uint32_t* r, uint32_t addr) {
    asm volatile("ldmatrix.sync.aligned.m8n8.x4.shared.b16 {%0,%1,%2,%3}, [%4];"
                 : "=r"(r[0]), "=r"(r[1]), "=r"(r[2]), "=r"(r[3]) : "r"(addr));
}
__device__ __forceinline__ void mma16816(float* d, const uint32_t* a,
                                         const uint32_t* b) {
    asm volatile(
        "mma.sync.aligned.m16n8k16.row.col.f32.f16.f16.f32 "
        "{%0,%1,%2,%3}, {%4,%5,%6,%7}, {%8,%9}, {%0,%1,%2,%3};"
        : "+f"(d[0]), "+f"(d[1]), "+f"(d[2]), "+f"(d[3])
        : "r"(a[0]), "r"(a[1]), "r"(a[2]), "r"(a[3]), "r"(b[0]), "r"(b[1]));
}
__device__ __forceinline__ float ex2f(float x) {
    float y; asm("ex2.approx.f32 %0, %1;" : "=f"(y) : "f"(x)); return y;
}
__device__ __forceinline__ float rcpf(float x) {
    float y; asm("rcp.approx.f32 %0, %1;" : "=f"(y) : "f"(x)); return y;
}
__device__ __forceinline__ float sigf(float x) {
    return rcpf(1.0f + ex2f(-1.4426950408889634f * x));
}
__device__ __forceinline__ float tanhf_fast(float x) {
    return 1.0f - 2.0f * rcpf(1.0f + ex2f(2.8853900817779268f * x));
}

// -------- merged conversion kernel --------
// blocks [0, CONVA_BLOCKS): A = fp16([X | H]), row-major [8192 x 1024]
// blocks [CONVA_BLOCKS, +CONVB_BLOCKS): B = fp16 transpose+permute of [W;R]
__global__ __launch_bounds__(256)
void conv_all(const float* __restrict__ X, const float* __restrict__ H,
              const float* __restrict__ W, const float* __restrict__ R)
{
    __shared__ __half s[64][34];
    if (blockIdx.x < CONVA_BLOCKS) {
        int idx = blockIdx.x * 256 + threadIdx.x;   // oct index, 1M total
        int row = idx >> 7;
        int c8  = (idx & 127) * 8;
        const float4* src = (c8 < 512)
            ? (const float4*)(X + (size_t)row * 512 + c8)
            : (const float4*)(H + (size_t)row * 512 + (c8 - 512));
        float4 v0 = src[0], v1 = src[1];
        __half h[8];
        h[0] = __float2half(v0.x); h[1] = __float2half(v0.y);
        h[2] = __float2half(v0.z); h[3] = __float2half(v0.w);
        h[4] = __float2half(v1.x); h[5] = __float2half(v1.y);
        h[6] = __float2half(v1.z); h[7] = __float2half(v1.w);
        ((uint4*)g_A)[idx] = *(uint4*)h;
    } else {
        int bb = blockIdx.x - CONVA_BLOCKS;
        const int c0 = (bb % CONVB_BX) * 32;
        const int k0 = (bb / CONVB_BX) * 64;
        #pragma unroll
        for (int i = 0; i < 8; ++i) {
            int idx = threadIdx.x + i * 256;   // 0..2047
            int kl = idx >> 5, cl = idx & 31;
            int colp = c0 + cl, u = colp >> 2, gate = colp & 3;
            int zcol = gate * 512 + u;
            int k = k0 + kl;
            float v = (k < 512) ? W[(size_t)k * NTOT + zcol]
                                : R[(size_t)(k - 512) * NTOT + zcol];
            s[kl][cl] = __float2half(v);
        }
        __syncthreads();
        const int cl = threadIdx.x >> 3;          // 0..31
        const int ks = (threadIdx.x & 7) * 8;     // 0..56
        __half tmp[8];
        #pragma unroll
        for (int j = 0; j < 8; ++j) tmp[j] = s[ks + j][cl];
        *(uint4*)&g_B[(size_t)(c0 + cl) * KK + k0 + ks] = *(uint4*)tmp;
    }
}

// -------- fused GEMM + gates (R5-proven) --------
__global__ __launch_bounds__(256, 2)
void lstm_mma(const float* __restrict__ Cprev,
              const float* __restrict__ bias,
              float* __restrict__ out)
{
    extern __shared__ __align__(128) char smem[];
    const uint32_t sm = s2u(smem);
    const int tid = threadIdx.x, wid = tid >> 5, lane = tid & 31;
    const int warp_m = wid >> 2;            // 0..1  (64 rows)
    const int warp_n = wid & 3;             // 0..3  (32 cols)
    const int m0 = blockIdx.y * BM;
    const int n0 = blockIdx.x * BN;

    float acc[4][4][4];
    #pragma unroll
    for (int mi = 0; mi < 4; ++mi)
        #pragma unroll
        for (int ni = 0; ni < 4; ++ni)
            #pragma unroll
            for (int r = 0; r < 4; ++r) acc[mi][ni][r] = 0.0f;

    const int lr0 = tid >> 2, lseg = tid & 3;

    auto load_stage = [&](int t, int stg) {
        const uint32_t sb = sm + stg * STAGEB;
        const int kb = t * BK;
        #pragma unroll
        for (int j = 0; j < 2; ++j) {
            int r = lr0 + j * 64;
            uint32_t dst = sb + r * ROWB + lseg * 16;
            cp16(dst,         g_A + (size_t)(m0 + r) * KK + kb + lseg * 8);
            cp16(dst + TILEB, g_B + (size_t)(n0 + r) * KK + kb + lseg * 8);
        }
    };

    load_stage(0, 0); CP_COMMIT();
    load_stage(1, 1); CP_COMMIT();
    load_stage(2, 2); CP_COMMIT();

    const uint32_t aoff = (warp_m * 64 + (lane & 15)) * ROWB + ((lane >> 4) << 4);
    const uint32_t boff = TILEB
        + (warp_n * 32 + (lane & 7) + ((lane & 16) >> 1)) * ROWB + ((lane & 8) << 1);

    for (int t = 0; t < KT; ++t) {
        CP_WAIT2();
        __syncthreads();

        const uint32_t sb = sm + (t & 3) * STAGEB;
        #pragma unroll
        for (int ks = 0; ks < 2; ++ks) {
            const uint32_t kB = ks * 32;
            uint32_t ah[4][4], bh[2][4];
            #pragma unroll
            for (int mi = 0; mi < 4; ++mi)
                ldsm4(ah[mi], sb + aoff + mi * (16 * ROWB) + kB);
            #pragma unroll
            for (int nj = 0; nj < 2; ++nj)
                ldsm4(bh[nj], sb + boff + nj * (16 * ROWB) + kB);

            #pragma unroll
            for (int mi = 0; mi < 4; ++mi)
                #pragma unroll
                for (int ni = 0; ni < 4; ++ni)
                    mma16816(acc[mi][ni], ah[mi], &bh[ni >> 1][(ni & 1) * 2]);
        }

        if (t + 3 < KT) load_stage(t + 3, (t + 3) & 3);
        CP_COMMIT();
    }

    // ---- epilogue: stage z through smem (operand buffers dead) ----
    __syncthreads();
    float* zs = (float*)smem;               // [128][132]
    const int g = lane >> 2, c2 = (lane & 3) * 2;
    #pragma unroll
    for (int mi = 0; mi < 4; ++mi) {
        const int r0 = warp_m * 64 + mi * 16 + g;
        #pragma unroll
        for (int ni = 0; ni < 4; ++ni) {
            const int col = warp_n * 32 + ni * 8 + c2;
            zs[r0 * 132 + col]           = acc[mi][ni][0];
            zs[r0 * 132 + col + 1]       = acc[mi][ni][1];
            zs[(r0 + 8) * 132 + col]     = acc[mi][ni][2];
            zs[(r0 + 8) * 132 + col + 1] = acc[mi][ni][3];
        }
    }
    __syncthreads();

    const size_t BU = (size_t)MB * UU;
    #pragma unroll
    for (int i = 0; i < 16; ++i) {
        int q   = tid + i * 256;            // 0..4095
        int row = q >> 5;
        int ul  = q & 31;
        float4 zq = *(float4*)&zs[row * 132 + ul * 4];
        int u = blockIdx.x * 32 + ul;
        float zi = zq.x + __ldg(bias + u);
        float zf = zq.y + __ldg(bias + 512 + u);
        float zg = zq.z + __ldg(bias + 1024 + u);
        float zo = zq.w + __ldg(bias + 1536 + u);
        float cp = Cprev[(size_t)(m0 + row) * UU + u];
        float cn = sigf(zf) * cp + sigf(zi) * tanhf_fast(zg);
        float hv = sigf(zo) * tanhf_fast(cn);
        size_t o = (size_t)(m0 + row) * UU + u;
        out[o]          = hv;
        out[o + BU]     = hv;
        out[o + 2 * BU] = cn;
    }
}

// -------- launch --------
extern "C" void kernel_launch(void* const* d_in, const int* in_sizes, int n_in,
                              void* d_out, int out_size)
{
    const float* X    = (const float*)d_in[0];
    const float* H    = (const float*)d_in[1];
    const float* C    = (const float*)d_in[2];
    const float* W    = (const float*)d_in[3];
    const float* R    = (const float*)d_in[4];
    const float* bias = (const float*)d_in[5];
    float* out = (float*)d_out;

    static bool attr_done = false;
    if (!attr_done) {
        cudaFuncSetAttribute(lstm_mma,
                             cudaFuncAttributeMaxDynamicSharedMemorySize, SMEM_DYN);
        attr_done = true;
    }

    conv_all<<<CONVA_BLOCKS + CONVB_BLOCKS, 256>>>(X, H, W, R);

    dim3 grid(NTOT / BN, MB / BM);          // (16, 64)
    lstm_mma<<<grid, 256, SMEM_DYN>>>(C, bias, out);
}